// round 16
// baseline (speedup 1.0000x reference)
#include <cuda_runtime.h>
#include <cstdint>
#include <cstddef>

// ============================================================================
// InteractionBlock (DimeNet-like). H = 128 fixed.
// Round 16: M-tile 32, 16-row W chunk ring -> smem 33.8KB, 4 blocks/SM
// (32 warps). Warp tile 16x32 (acc=16 regs, no spills at 64-reg cap).
// sbfh rewritten with coalesced smem staging.
// ============================================================================

#define MAX_E 50000
#define MAX_T 200000

__device__ float    g_rbfh[MAX_E * 128];
__device__ float    g_xkj [MAX_E * 128];
__device__ float    g_h   [MAX_E * 128];
__device__ float    g_tmp [MAX_E * 128];
__device__ float    g_sbfh[MAX_T * 8];
__device__ uint32_t g_Wt  [8 * 128 * 128];   // tf32 [j][k][n] = Wbil[n][j][k]
__device__ uint32_t g_wtf [10 * 128 * 128];  // tf32 dense weights, [k][n]
__device__ float    g_y   [MAX_E * 1024];    // y[e][j*128+n]

__device__ __forceinline__ float silu_f(float v) {
    return v / (1.0f + __expf(-v));
}

__device__ __forceinline__ uint32_t f2tf32(float f) {
    uint32_t u;
    asm("cvt.rna.tf32.f32 %0, %1;" : "=r"(u) : "f"(f));
    return u;
}

__device__ __forceinline__ void mma_tf32(float c[4],
                                         uint32_t a0, uint32_t a1,
                                         uint32_t a2, uint32_t a3,
                                         uint32_t b0, uint32_t b1) {
    asm("mma.sync.aligned.m16n8k8.row.col.f32.tf32.tf32.f32 "
        "{%0,%1,%2,%3}, {%4,%5,%6,%7}, {%8,%9}, {%0,%1,%2,%3};"
        : "+f"(c[0]), "+f"(c[1]), "+f"(c[2]), "+f"(c[3])
        : "r"(a0), "r"(a1), "r"(a2), "r"(a3), "r"(b0), "r"(b1));
}

__device__ __forceinline__ void cp_async16(void* smem_dst, const void* gl_src) {
    uint32_t s = (uint32_t)__cvta_generic_to_shared(smem_dst);
    asm volatile("cp.async.cg.shared.global [%0], [%1], 16;\n" :: "r"(s), "l"(gl_src));
}
__device__ __forceinline__ void cp_async_commit() {
    asm volatile("cp.async.commit_group;\n" ::: "memory");
}
__device__ __forceinline__ void cp_async_wait0() {
    asm volatile("cp.async.wait_group 0;\n" ::: "memory");
}

// ---------------------------------------------------------------------------
// Prep kernels
// ---------------------------------------------------------------------------
struct WSrc { const float* p[10]; };

__global__ void convert_weights(WSrc ws) {
    int gid = blockIdx.x * blockDim.x + threadIdx.x;
    if (gid >= 10 * 16384) return;
    int w = gid >> 14, idx = gid & 16383;
    g_wtf[gid] = f2tf32(ws.p[w][idx]);
}

// g_Wt[j][k][n] = tf32(Wbil[n][j][k])
__global__ void transpose_wbil(const float* __restrict__ Wbil) {
    int gid = blockIdx.x * blockDim.x + threadIdx.x;
    if (gid >= 8 * 128 * 128) return;
    int n = gid & 127;
    int k = (gid >> 7) & 127;
    int j = gid >> 14;
    g_Wt[gid] = f2tf32(Wbil[n * 1024 + j * 128 + k]);
}

__global__ void rbfh_kernel(const float* __restrict__ rbf,
                            const float* __restrict__ Wrbf, int E) {
    int gid = blockIdx.x * blockDim.x + threadIdx.x;
    if (gid >= E * 128) return;
    int e = gid >> 7, n = gid & 127;
    float acc = 0.0f;
#pragma unroll
    for (int i = 0; i < 6; i++) acc += rbf[e * 6 + i] * Wrbf[i * 128 + n];
    g_rbfh[gid] = acc;
}

// Coalesced: stage 256 rows (contiguous span) + W_sbf in smem, then compute.
__global__ void __launch_bounds__(256)
sbfh_kernel(const float* __restrict__ sbf,
            const float* __restrict__ Wsbf, int T) {
    __shared__ float ss[256 * 43];   // padded rows, stride 43 (conflict-free)
    __shared__ float ws[42 * 8];
    const int tid = threadIdx.x;
    const int t0  = blockIdx.x * 256;
    const int nrows = min(256, T - t0);

    int total = nrows * 42;
    const float* src = sbf + (size_t)t0 * 42;
    for (int i = tid; i < total; i += 256) {
        int r = i / 42, c = i - r * 42;
        ss[r * 43 + c] = src[i];
    }
    for (int i = tid; i < 336; i += 256) ws[i] = Wsbf[i];
    __syncthreads();

    int t = t0 + tid;
    if (t >= T) return;
    float acc[8];
#pragma unroll
    for (int j = 0; j < 8; j++) acc[j] = 0.0f;
    const float* row = ss + tid * 43;
#pragma unroll
    for (int i = 0; i < 42; i++) {
        float s = row[i];
#pragma unroll
        for (int j = 0; j < 8; j++) acc[j] += s * ws[i * 8 + j];
    }
    float4* o = (float4*)(g_sbfh + (size_t)t * 8);
    o[0] = make_float4(acc[0], acc[1], acc[2], acc[3]);
    o[1] = make_float4(acc[4], acc[5], acc[6], acc[7]);
}

// ---------------------------------------------------------------------------
// TF32 GEMM building blocks.
// smem (uint32): As[32][132] + Wb[2][16][132] = 8448 words = 33792 B.
// Block = 256 thr (8 warps, 2(M) x 4(N)), tile 32(M) x 128(N), K=128.
// Warp tile 16x32: 1 m16-tile x 4 n8-tiles. W streamed in 8 chunks of 16
// k-rows, double-buffered. 4 blocks/SM.
// ---------------------------------------------------------------------------
#define AS_LD 132
#define BM    32
#define WROWS 16
#define WCH   (WROWS * AS_LD)                       // words per W chunk buffer
#define SMEM_TF32 ((BM * AS_LD + 2 * WCH) * 4)      // 33792 B
#define NTHR  256

__device__ __forceinline__ void load_convert_A(const float* __restrict__ A,
                                               uint32_t* __restrict__ As,
                                               int brow, int M, int tid) {
    const float4* Ag = (const float4*)A;
#pragma unroll
    for (int it = 0; it < 4; it++) {
        int i = it * NTHR + tid;
        int r = i >> 5, c4 = i & 31;
        float4 v = make_float4(0.f, 0.f, 0.f, 0.f);
        if (brow + r < M) v = Ag[(size_t)(brow + r) * 32 + c4];
        uint4 t;
        t.x = f2tf32(v.x); t.y = f2tf32(v.y);
        t.z = f2tf32(v.z); t.w = f2tf32(v.w);
        *(uint4*)&As[r * AS_LD + c4 * 4] = t;
    }
}

// issue one 16-row W chunk (tf32 source, raw copy) into Wb
__device__ __forceinline__ void issue_wchunk(const uint32_t* __restrict__ Wsrc,
                                             uint32_t* __restrict__ Wb,
                                             int chunk, int tid) {
    const uint32_t* src = Wsrc + chunk * WROWS * 128;
#pragma unroll
    for (int q = 0; q < 2; q++) {
        int i = q * NTHR + tid;
        int r = i >> 5, c4 = i & 31;
        cp_async16(&Wb[r * AS_LD + c4 * 4], &src[r * 128 + c4 * 4]);
    }
    cp_async_commit();
}

// 2 k-steps (one 16-row chunk). kb0 = global k base of the chunk.
__device__ __forceinline__ void compute_chunk(const uint32_t* __restrict__ As,
                                              const uint32_t* __restrict__ Wc,
                                              int kb0, int warp_m, int warp_n,
                                              int gid, int tig,
                                              float acc[4][4]) {
#pragma unroll
    for (int ksl = 0; ksl < 2; ksl++) {
        int kb = kb0 + ksl * 8;       // for A (global k)
        int kl = ksl * 8;             // local k within chunk
        uint32_t a[4];
        {
            int r0 = warp_m * 16 + gid;
            a[0] = As[r0 * AS_LD + kb + tig];
            a[1] = As[(r0 + 8) * AS_LD + kb + tig];
            a[2] = As[r0 * AS_LD + kb + tig + 4];
            a[3] = As[(r0 + 8) * AS_LD + kb + tig + 4];
        }
        uint32_t b[4][2];
#pragma unroll
        for (int nt = 0; nt < 4; nt++) {
            int n = warp_n * 32 + nt * 8 + gid;
            b[nt][0] = Wc[(kl + tig) * AS_LD + n];
            b[nt][1] = Wc[(kl + tig + 4) * AS_LD + n];
        }
#pragma unroll
        for (int nt = 0; nt < 4; nt++)
            mma_tf32(acc[nt], a[0], a[1], a[2], a[3], b[nt][0], b[nt][1]);
    }
}

// Full K=128 GEMM on resident As with streamed W. Leaves NO trailing sync:
// caller must __syncthreads() before anything overwrites Wb.
__device__ __forceinline__ void gemm_streamW(const uint32_t* __restrict__ As,
                                             uint32_t* __restrict__ Wb,
                                             const uint32_t* __restrict__ Wsrc,
                                             int tid, int warp_m, int warp_n,
                                             int gid, int tig,
                                             float acc[4][4]) {
#pragma unroll
    for (int nt = 0; nt < 4; nt++)
#pragma unroll
        for (int c = 0; c < 4; c++) acc[nt][c] = 0.0f;

    issue_wchunk(Wsrc, Wb, 0, tid);
    cp_async_wait0();
    __syncthreads();

#pragma unroll 1
    for (int c = 0; c < 8; c++) {
        if (c < 7) issue_wchunk(Wsrc, Wb + ((c + 1) & 1) * WCH, c + 1, tid);
        compute_chunk(As, Wb + (c & 1) * WCH, c * WROWS,
                      warp_m, warp_n, gid, tig, acc);
        if (c < 7) {
            cp_async_wait0();
            __syncthreads();
        }
    }
}

// Epilogue modes
#define M_SILU     0
#define M_SILU_MUL 1
#define M_SILU_ADD 2
#define M_PLAIN    3

template <int MODE>
__device__ __forceinline__ void epilogue_tf32(const float acc[4][4],
                                              const float* __restrict__ bias,
                                              const float* __restrict__ extra,
                                              float* __restrict__ Cg, int ldc,
                                              int brow, int M,
                                              int warp_m, int warp_n,
                                              int gid, int tig) {
    int rbase = brow + warp_m * 16 + gid;
#pragma unroll
    for (int half = 0; half < 2; half++) {
        int row = rbase + half * 8;
        if (row >= M) continue;
#pragma unroll
        for (int nt = 0; nt < 4; nt++) {
            int n = warp_n * 32 + nt * 8 + tig * 2;
            float v0 = acc[nt][half * 2];
            float v1 = acc[nt][half * 2 + 1];
            if (MODE != M_PLAIN) {
                v0 = silu_f(v0 + bias[n]);
                v1 = silu_f(v1 + bias[n + 1]);
            }
            if (MODE == M_SILU_MUL) {
                float2 e = *(const float2*)&extra[(size_t)row * 128 + n];
                v0 *= e.x; v1 *= e.y;
            } else if (MODE == M_SILU_ADD) {
                float2 e = *(const float2*)&extra[(size_t)row * 128 + n];
                v0 += e.x; v1 += e.y;
            }
            float2 st; st.x = v0; st.y = v1;
            *(float2*)&Cg[(size_t)row * ldc + n] = st;
        }
    }
}

// ---------------------------------------------------------------------------
// Generic single GEMM (W = pre-converted tf32 [k][n])
// ---------------------------------------------------------------------------
template <int MODE>
__global__ void __launch_bounds__(NTHR, 4)
tf32_gemm(const float* __restrict__ A, const uint32_t* __restrict__ Wtf,
          const float* __restrict__ bias, const float* __restrict__ extra,
          float* __restrict__ C, int ldc, int M) {
    extern __shared__ uint32_t smu[];
    uint32_t* As = smu;
    uint32_t* Wb = smu + BM * AS_LD;
    const int tid = threadIdx.x, brow = blockIdx.x * BM;
    const int warp = tid >> 5, lane = tid & 31;
    const int warp_m = warp >> 2, warp_n = warp & 3;
    const int gid = lane >> 2, tig = lane & 3;

    load_convert_A(A, As, brow, M, tid);
    // gemm_streamW's first wait+sync also fences As stores.
    float acc[4][4];
    gemm_streamW(As, Wb, Wtf, tid, warp_m, warp_n, gid, tig, acc);
    epilogue_tf32<MODE>(acc, bias, extra, C, ldc, brow, M, warp_m, warp_n, gid, tig);
}

// ---------------------------------------------------------------------------
// Stage A fused: h = silu(x@Wji+bji) ; xkj = silu(x@Wkj+bkj) * rbfh
// ---------------------------------------------------------------------------
__global__ void __launch_bounds__(NTHR, 4)
dualA_tf32(const float* __restrict__ x,
           const uint32_t* __restrict__ Wji_t, const float* __restrict__ bji,
           const uint32_t* __restrict__ Wkj_t, const float* __restrict__ bkj,
           float* __restrict__ h, float* __restrict__ xkj, int M) {
    extern __shared__ uint32_t smu[];
    uint32_t* As = smu;
    uint32_t* Wb = smu + BM * AS_LD;
    const int tid = threadIdx.x, brow = blockIdx.x * BM;
    const int warp = tid >> 5, lane = tid & 31;
    const int warp_m = warp >> 2, warp_n = warp & 3;
    const int gid = lane >> 2, tig = lane & 3;

    load_convert_A(x, As, brow, M, tid);
    {
        float acc[4][4];
        gemm_streamW(As, Wb, Wji_t, tid, warp_m, warp_n, gid, tig, acc);
        epilogue_tf32<M_SILU>(acc, bji, nullptr, h, 128, brow, M,
                              warp_m, warp_n, gid, tig);
    }
    __syncthreads();   // all Wb reads done before next stream overwrites
    {
        float acc[4][4];
        gemm_streamW(As, Wb, Wkj_t, tid, warp_m, warp_n, gid, tig, acc);
        epilogue_tf32<M_SILU_MUL>(acc, bkj, g_rbfh, xkj, 128, brow, M,
                                  warp_m, warp_n, gid, tig);
    }
}

// ---------------------------------------------------------------------------
// Stage B1: y[e, j*128+n] = sum_k xkj[e,k]*Wt[j,k,n] — A-tile reused over j.
// ---------------------------------------------------------------------------
__global__ void __launch_bounds__(NTHR, 4)
ygemm_tf32(const float* __restrict__ xkj, float* __restrict__ Y, int M) {
    extern __shared__ uint32_t smu[];
    uint32_t* As = smu;
    uint32_t* Wb = smu + BM * AS_LD;
    const int tid = threadIdx.x, brow = blockIdx.x * BM;
    const int warp = tid >> 5, lane = tid & 31;
    const int warp_m = warp >> 2, warp_n = warp & 3;
    const int gid = lane >> 2, tig = lane & 3;

    load_convert_A(xkj, As, brow, M, tid);

#pragma unroll 1
    for (int j = 0; j < 8; j++) {
        float acc[4][4];
        gemm_streamW(As, Wb, g_Wt + j * 16384, tid, warp_m, warp_n, gid, tig, acc);
        epilogue_tf32<M_PLAIN>(acc, nullptr, nullptr, Y + j * 128, 1024,
                               brow, M, warp_m, warp_n, gid, tig);
        __syncthreads();   // Wb reads done before next j's stream
    }
}

// ---------------------------------------------------------------------------
// Combine + scatter: one warp per triplet.
// ---------------------------------------------------------------------------
__global__ void __launch_bounds__(256)
combine_kernel(const float* __restrict__ Y,
               const int* __restrict__ idx_kj, const int* __restrict__ idx_ji,
               float* __restrict__ h, int T) {
    int t = blockIdx.x * 8 + (threadIdx.x >> 5);
    if (t >= T) return;
    int lane = threadIdx.x & 31;

    int ekj = __ldg(&idx_kj[t]);
    int eji = __ldg(&idx_ji[t]);
    const float4* s4 = (const float4*)(g_sbfh + (size_t)t * 8);
    float4 sA = s4[0], sB = s4[1];
    float s[8] = {sA.x, sA.y, sA.z, sA.w, sB.x, sB.y, sB.z, sB.w};

    const float4* yr = (const float4*)(Y + (size_t)ekj * 1024);
    float4 acc = make_float4(0.f, 0.f, 0.f, 0.f);
#pragma unroll
    for (int j = 0; j < 8; j++) {
        float4 v = __ldg(&yr[j * 32 + lane]);
        acc.x += s[j] * v.x;
        acc.y += s[j] * v.y;
        acc.z += s[j] * v.z;
        acc.w += s[j] * v.w;
    }
    atomicAdd(&((float4*)h)[(size_t)eji * 32 + lane], acc);
}

// ---------------------------------------------------------------------------
// Host launcher
// ---------------------------------------------------------------------------
extern "C" void kernel_launch(void* const* d_in, const int* in_sizes, int n_in,
                              void* d_out, int out_size) {
    const float* x      = (const float*)d_in[0];
    const float* rbf    = (const float*)d_in[1];
    const float* sbf    = (const float*)d_in[2];
    const int*   idx_kj = (const int*)d_in[3];
    const int*   idx_ji = (const int*)d_in[4];
    const float* W_rbf  = (const float*)d_in[5];
    const float* W_sbf  = (const float*)d_in[6];
    const float* Wkj    = (const float*)d_in[7];
    const float* bkj    = (const float*)d_in[8];
    const float* Wji    = (const float*)d_in[9];
    const float* bji    = (const float*)d_in[10];
    const float* Wbil   = (const float*)d_in[11];
    const float* bW1    = (const float*)d_in[12];
    const float* bb1    = (const float*)d_in[13];
    const float* bW2    = (const float*)d_in[14];
    const float* bb2    = (const float*)d_in[15];
    const float* Wlin   = (const float*)d_in[16];
    const float* blin   = (const float*)d_in[17];
    const float* aW1    = (const float*)d_in[18];
    const float* ab1    = (const float*)d_in[19];
    const float* aW2    = (const float*)d_in[20];
    const float* ab2    = (const float*)d_in[21];
    const float* Wout   = (const float*)d_in[22];
    const float* bout   = (const float*)d_in[23];
    float* out = (float*)d_out;

    const int E = in_sizes[0] / 128;
    const int T = in_sizes[3];

    float *xkj, *h, *tmp, *y;
    uint32_t* wtf;
    cudaGetSymbolAddress((void**)&xkj, g_xkj);
    cudaGetSymbolAddress((void**)&h,   g_h);
    cudaGetSymbolAddress((void**)&tmp, g_tmp);
    cudaGetSymbolAddress((void**)&y,   g_y);
    cudaGetSymbolAddress((void**)&wtf, g_wtf);

    cudaFuncSetAttribute(tf32_gemm<M_SILU>,     cudaFuncAttributeMaxDynamicSharedMemorySize, SMEM_TF32);
    cudaFuncSetAttribute(tf32_gemm<M_SILU_ADD>, cudaFuncAttributeMaxDynamicSharedMemorySize, SMEM_TF32);
    cudaFuncSetAttribute(dualA_tf32,            cudaFuncAttributeMaxDynamicSharedMemorySize, SMEM_TF32);
    cudaFuncSetAttribute(ygemm_tf32,            cudaFuncAttributeMaxDynamicSharedMemorySize, SMEM_TF32);

    // Stage 0: preps
    WSrc ws;
    ws.p[0] = Wji;  ws.p[1] = Wkj;
    ws.p[2] = bW1;  ws.p[3] = bW2;
    ws.p[4] = Wlin;
    ws.p[5] = aW1;          ws.p[6] = aW2;
    ws.p[7] = aW1 + 16384;  ws.p[8] = aW2 + 16384;
    ws.p[9] = Wout;
    convert_weights<<<(10 * 16384 + 255) / 256, 256>>>(ws);
    transpose_wbil<<<(8 * 128 * 128 + 255) / 256, 256>>>(Wbil);
    rbfh_kernel<<<(E * 128 + 255) / 256, 256>>>(rbf, W_rbf, E);
    sbfh_kernel<<<(T + 255) / 256, 256>>>(sbf, W_sbf, T);

    const int gE = (E + BM - 1) / BM;
    const uint32_t* WjiT  = wtf + 0 * 16384;
    const uint32_t* WkjT  = wtf + 1 * 16384;
    const uint32_t* bW1T  = wtf + 2 * 16384;
    const uint32_t* bW2T  = wtf + 3 * 16384;
    const uint32_t* WlinT = wtf + 4 * 16384;
    const uint32_t* aW1T0 = wtf + 5 * 16384;
    const uint32_t* aW2T0 = wtf + 6 * 16384;
    const uint32_t* aW1T1 = wtf + 7 * 16384;
    const uint32_t* aW2T1 = wtf + 8 * 16384;
    const uint32_t* WoutT = wtf + 9 * 16384;

    // Stage A
    dualA_tf32<<<gE, NTHR, SMEM_TF32>>>(x, WjiT, bji, WkjT, bkj, h, xkj, E);

    // Stage B1: y precompute
    ygemm_tf32<<<gE, NTHR, SMEM_TF32>>>(xkj, y, E);

    // Stage B2: combine + scatter into h  => h = x_ji + agg
    combine_kernel<<<(T + 7) / 8, 256>>>(y, idx_kj, idx_ji, h, T);

    // Stage C: h += silu(silu(h@bW1+bb1)@bW2+bb2)
    tf32_gemm<M_SILU><<<gE, NTHR, SMEM_TF32>>>(h,   bW1T, bb1, nullptr, tmp, 128, E);
    tf32_gemm<M_SILU_ADD><<<gE, NTHR, SMEM_TF32>>>(tmp, bW2T, bb2, h,    h,   128, E);

    // Stage D: h = silu(h@Wlin+blin) + x
    tf32_gemm<M_SILU_ADD><<<gE, NTHR, SMEM_TF32>>>(h, WlinT, blin, x, h, 128, E);

    // Stage E (2x)
    tf32_gemm<M_SILU><<<gE, NTHR, SMEM_TF32>>>(h,   aW1T0, ab1,       nullptr, tmp, 128, E);
    tf32_gemm<M_SILU_ADD><<<gE, NTHR, SMEM_TF32>>>(tmp, aW2T0, ab2,       h,   h,   128, E);
    tf32_gemm<M_SILU><<<gE, NTHR, SMEM_TF32>>>(h,   aW1T1, ab1 + 128, nullptr, tmp, 128, E);
    tf32_gemm<M_SILU_ADD><<<gE, NTHR, SMEM_TF32>>>(tmp, aW2T1, ab2 + 128, h,   h,   128, E);

    // Stage F: out = silu(h@Wout+bout)
    tf32_gemm<M_SILU><<<gE, NTHR, SMEM_TF32>>>(h, WoutT, bout, nullptr, out, 128, E);
}

// round 17
// speedup vs baseline: 1.2469x; 1.2469x over previous
#include <cuda_runtime.h>
#include <cuda_fp16.h>
#include <cstdint>
#include <cstddef>

// ============================================================================
// InteractionBlock (DimeNet-like). H = 128 fixed.
// Round 17: R15 GEMM core (BM=64, 32-row W ring, 3 blocks/SM — proven 578us)
//  + coalesced sbfh (R16, proven)
//  + y stored as fp16 (halves ygemm-write and combine-read traffic).
// ============================================================================

#define MAX_E 50000
#define MAX_T 200000

__device__ float    g_rbfh[MAX_E * 128];
__device__ float    g_xkj [MAX_E * 128];
__device__ float    g_h   [MAX_E * 128];
__device__ float    g_tmp [MAX_E * 128];
__device__ float    g_sbfh[MAX_T * 8];
__device__ uint32_t g_Wt  [8 * 128 * 128];   // tf32 [j][k][n] = Wbil[n][j][k]
__device__ uint32_t g_wtf [10 * 128 * 128];  // tf32 dense weights, [k][n]
__device__ uint32_t g_y   [MAX_E * 512];     // fp16x2: y[e][j*64 + n/2]

__device__ __forceinline__ float silu_f(float v) {
    return v / (1.0f + __expf(-v));
}

__device__ __forceinline__ uint32_t f2tf32(float f) {
    uint32_t u;
    asm("cvt.rna.tf32.f32 %0, %1;" : "=r"(u) : "f"(f));
    return u;
}

__device__ __forceinline__ void mma_tf32(float c[4],
                                         uint32_t a0, uint32_t a1,
                                         uint32_t a2, uint32_t a3,
                                         uint32_t b0, uint32_t b1) {
    asm("mma.sync.aligned.m16n8k8.row.col.f32.tf32.tf32.f32 "
        "{%0,%1,%2,%3}, {%4,%5,%6,%7}, {%8,%9}, {%0,%1,%2,%3};"
        : "+f"(c[0]), "+f"(c[1]), "+f"(c[2]), "+f"(c[3])
        : "r"(a0), "r"(a1), "r"(a2), "r"(a3), "r"(b0), "r"(b1));
}

__device__ __forceinline__ void cp_async16(void* smem_dst, const void* gl_src) {
    uint32_t s = (uint32_t)__cvta_generic_to_shared(smem_dst);
    asm volatile("cp.async.cg.shared.global [%0], [%1], 16;\n" :: "r"(s), "l"(gl_src));
}
__device__ __forceinline__ void cp_async_commit() {
    asm volatile("cp.async.commit_group;\n" ::: "memory");
}
__device__ __forceinline__ void cp_async_wait0() {
    asm volatile("cp.async.wait_group 0;\n" ::: "memory");
}

// ---------------------------------------------------------------------------
// Prep kernels
// ---------------------------------------------------------------------------
struct WSrc { const float* p[10]; };

__global__ void convert_weights(WSrc ws) {
    int gid = blockIdx.x * blockDim.x + threadIdx.x;
    if (gid >= 10 * 16384) return;
    int w = gid >> 14, idx = gid & 16383;
    g_wtf[gid] = f2tf32(ws.p[w][idx]);
}

// g_Wt[j][k][n] = tf32(Wbil[n][j][k])
__global__ void transpose_wbil(const float* __restrict__ Wbil) {
    int gid = blockIdx.x * blockDim.x + threadIdx.x;
    if (gid >= 8 * 128 * 128) return;
    int n = gid & 127;
    int k = (gid >> 7) & 127;
    int j = gid >> 14;
    g_Wt[gid] = f2tf32(Wbil[n * 1024 + j * 128 + k]);
}

__global__ void rbfh_kernel(const float* __restrict__ rbf,
                            const float* __restrict__ Wrbf, int E) {
    int gid = blockIdx.x * blockDim.x + threadIdx.x;
    if (gid >= E * 128) return;
    int e = gid >> 7, n = gid & 127;
    float acc = 0.0f;
#pragma unroll
    for (int i = 0; i < 6; i++) acc += rbf[e * 6 + i] * Wrbf[i * 128 + n];
    g_rbfh[gid] = acc;
}

// Coalesced: stage 256 rows (contiguous span) + W_sbf in smem, then compute.
__global__ void __launch_bounds__(256)
sbfh_kernel(const float* __restrict__ sbf,
            const float* __restrict__ Wsbf, int T) {
    __shared__ float ss[256 * 43];   // padded rows, stride 43 (conflict-free)
    __shared__ float ws[42 * 8];
    const int tid = threadIdx.x;
    const int t0  = blockIdx.x * 256;
    const int nrows = min(256, T - t0);

    int total = nrows * 42;
    const float* src = sbf + (size_t)t0 * 42;
    for (int i = tid; i < total; i += 256) {
        int r = i / 42, c = i - r * 42;
        ss[r * 43 + c] = src[i];
    }
    for (int i = tid; i < 336; i += 256) ws[i] = Wsbf[i];
    __syncthreads();

    int t = t0 + tid;
    if (t >= T) return;
    float acc[8];
#pragma unroll
    for (int j = 0; j < 8; j++) acc[j] = 0.0f;
    const float* row = ss + tid * 43;
#pragma unroll
    for (int i = 0; i < 42; i++) {
        float s = row[i];
#pragma unroll
        for (int j = 0; j < 8; j++) acc[j] += s * ws[i * 8 + j];
    }
    float4* o = (float4*)(g_sbfh + (size_t)t * 8);
    o[0] = make_float4(acc[0], acc[1], acc[2], acc[3]);
    o[1] = make_float4(acc[4], acc[5], acc[6], acc[7]);
}

// ---------------------------------------------------------------------------
// TF32 GEMM building blocks (R15 config).
// smem (uint32): As[64][132] + Wb[2][32][132] = 16896 words = 67584 B.
// Block = 256 thr (8 warps, 2(M) x 4(N)), tile 64(M) x 128(N), K=128.
// Warp tile 32x32. W streamed in 4 chunks of 32 k-rows, double-buffered.
// ---------------------------------------------------------------------------
#define AS_LD 132
#define WCH   (32 * AS_LD)                      // words per W chunk buffer
#define SMEM_TF32 ((64 * AS_LD + 2 * WCH) * 4)  // 67584 B
#define NTHR 256

__device__ __forceinline__ void load_convert_A(const float* __restrict__ A,
                                               uint32_t* __restrict__ As,
                                               int brow, int M, int tid) {
    const float4* Ag = (const float4*)A;
#pragma unroll
    for (int it = 0; it < 8; it++) {
        int i = it * NTHR + tid;
        int r = i >> 5, c4 = i & 31;
        float4 v = make_float4(0.f, 0.f, 0.f, 0.f);
        if (brow + r < M) v = Ag[(size_t)(brow + r) * 32 + c4];
        uint4 t;
        t.x = f2tf32(v.x); t.y = f2tf32(v.y);
        t.z = f2tf32(v.z); t.w = f2tf32(v.w);
        *(uint4*)&As[r * AS_LD + c4 * 4] = t;
    }
}

// issue one 32-row W chunk (tf32 source, raw copy) into Wb
__device__ __forceinline__ void issue_wchunk(const uint32_t* __restrict__ Wsrc,
                                             uint32_t* __restrict__ Wb,
                                             int chunk, int tid) {
    const uint32_t* src = Wsrc + chunk * 32 * 128;
#pragma unroll
    for (int q = 0; q < 4; q++) {
        int i = q * NTHR + tid;
        int r = i >> 5, c4 = i & 31;
        cp_async16(&Wb[r * AS_LD + c4 * 4], &src[r * 128 + c4 * 4]);
    }
    cp_async_commit();
}

// 4 k-steps (one 32-row chunk). kb0 = global k base of the chunk.
__device__ __forceinline__ void compute_chunk(const uint32_t* __restrict__ As,
                                              const uint32_t* __restrict__ Wc,
                                              int kb0, int warp_m, int warp_n,
                                              int gid, int tig,
                                              float acc[2][4][4]) {
#pragma unroll
    for (int ksl = 0; ksl < 4; ksl++) {
        int kb = kb0 + ksl * 8;       // for A (global k)
        int kl = ksl * 8;             // local k within chunk
        uint32_t a[2][4];
#pragma unroll
        for (int mt = 0; mt < 2; mt++) {
            int r0 = warp_m * 32 + mt * 16 + gid;
            a[mt][0] = As[r0 * AS_LD + kb + tig];
            a[mt][1] = As[(r0 + 8) * AS_LD + kb + tig];
            a[mt][2] = As[r0 * AS_LD + kb + tig + 4];
            a[mt][3] = As[(r0 + 8) * AS_LD + kb + tig + 4];
        }
        uint32_t b[4][2];
#pragma unroll
        for (int nt = 0; nt < 4; nt++) {
            int n = warp_n * 32 + nt * 8 + gid;
            b[nt][0] = Wc[(kl + tig) * AS_LD + n];
            b[nt][1] = Wc[(kl + tig + 4) * AS_LD + n];
        }
#pragma unroll
        for (int mt = 0; mt < 2; mt++)
#pragma unroll
            for (int nt = 0; nt < 4; nt++)
                mma_tf32(acc[mt][nt], a[mt][0], a[mt][1], a[mt][2], a[mt][3],
                         b[nt][0], b[nt][1]);
    }
}

// Full K=128 GEMM on resident As with streamed W. Leaves NO trailing sync:
// caller must __syncthreads() before anything overwrites Wb.
__device__ __forceinline__ void gemm_streamW(const uint32_t* __restrict__ As,
                                             uint32_t* __restrict__ Wb,
                                             const uint32_t* __restrict__ Wsrc,
                                             int tid, int warp_m, int warp_n,
                                             int gid, int tig,
                                             float acc[2][4][4]) {
#pragma unroll
    for (int mt = 0; mt < 2; mt++)
#pragma unroll
        for (int nt = 0; nt < 4; nt++)
#pragma unroll
            for (int c = 0; c < 4; c++) acc[mt][nt][c] = 0.0f;

    issue_wchunk(Wsrc, Wb, 0, tid);
    cp_async_wait0();
    __syncthreads();

#pragma unroll 1
    for (int c = 0; c < 4; c++) {
        if (c < 3) issue_wchunk(Wsrc, Wb + ((c + 1) & 1) * WCH, c + 1, tid);
        compute_chunk(As, Wb + (c & 1) * WCH, c * 32,
                      warp_m, warp_n, gid, tig, acc);
        if (c < 3) {
            cp_async_wait0();
            __syncthreads();
        }
    }
}

// Epilogue modes
#define M_SILU     0
#define M_SILU_MUL 1
#define M_SILU_ADD 2

template <int MODE>
__device__ __forceinline__ void epilogue_tf32(const float acc[2][4][4],
                                              const float* __restrict__ bias,
                                              const float* __restrict__ extra,
                                              float* __restrict__ Cg, int ldc,
                                              int brow, int M,
                                              int warp_m, int warp_n,
                                              int gid, int tig) {
#pragma unroll
    for (int mt = 0; mt < 2; mt++) {
        int rbase = brow + warp_m * 32 + mt * 16 + gid;
#pragma unroll
        for (int half = 0; half < 2; half++) {
            int row = rbase + half * 8;
            if (row >= M) continue;
#pragma unroll
            for (int nt = 0; nt < 4; nt++) {
                int n = warp_n * 32 + nt * 8 + tig * 2;
                float v0 = acc[mt][nt][half * 2];
                float v1 = acc[mt][nt][half * 2 + 1];
                v0 = silu_f(v0 + bias[n]);
                v1 = silu_f(v1 + bias[n + 1]);
                if (MODE == M_SILU_MUL) {
                    float2 e = *(const float2*)&extra[(size_t)row * 128 + n];
                    v0 *= e.x; v1 *= e.y;
                } else if (MODE == M_SILU_ADD) {
                    float2 e = *(const float2*)&extra[(size_t)row * 128 + n];
                    v0 += e.x; v1 += e.y;
                }
                float2 st; st.x = v0; st.y = v1;
                *(float2*)&Cg[(size_t)row * ldc + n] = st;
            }
        }
    }
}

// ---------------------------------------------------------------------------
// Generic single GEMM (W = pre-converted tf32 [k][n])
// ---------------------------------------------------------------------------
template <int MODE>
__global__ void __launch_bounds__(NTHR, 3)
tf32_gemm(const float* __restrict__ A, const uint32_t* __restrict__ Wtf,
          const float* __restrict__ bias, const float* __restrict__ extra,
          float* __restrict__ C, int ldc, int M) {
    extern __shared__ uint32_t smu[];
    uint32_t* As = smu;
    uint32_t* Wb = smu + 64 * AS_LD;
    const int tid = threadIdx.x, brow = blockIdx.x * 64;
    const int warp = tid >> 5, lane = tid & 31;
    const int warp_m = warp >> 2, warp_n = warp & 3;
    const int gid = lane >> 2, tig = lane & 3;

    load_convert_A(A, As, brow, M, tid);
    // gemm_streamW's first wait+sync also fences As stores.
    float acc[2][4][4];
    gemm_streamW(As, Wb, Wtf, tid, warp_m, warp_n, gid, tig, acc);
    epilogue_tf32<MODE>(acc, bias, extra, C, ldc, brow, M, warp_m, warp_n, gid, tig);
}

// ---------------------------------------------------------------------------
// Stage A fused: h = silu(x@Wji+bji) ; xkj = silu(x@Wkj+bkj) * rbfh
// ---------------------------------------------------------------------------
__global__ void __launch_bounds__(NTHR, 3)
dualA_tf32(const float* __restrict__ x,
           const uint32_t* __restrict__ Wji_t, const float* __restrict__ bji,
           const uint32_t* __restrict__ Wkj_t, const float* __restrict__ bkj,
           float* __restrict__ h, float* __restrict__ xkj, int M) {
    extern __shared__ uint32_t smu[];
    uint32_t* As = smu;
    uint32_t* Wb = smu + 64 * AS_LD;
    const int tid = threadIdx.x, brow = blockIdx.x * 64;
    const int warp = tid >> 5, lane = tid & 31;
    const int warp_m = warp >> 2, warp_n = warp & 3;
    const int gid = lane >> 2, tig = lane & 3;

    load_convert_A(x, As, brow, M, tid);
    {
        float acc[2][4][4];
        gemm_streamW(As, Wb, Wji_t, tid, warp_m, warp_n, gid, tig, acc);
        epilogue_tf32<M_SILU>(acc, bji, nullptr, h, 128, brow, M,
                              warp_m, warp_n, gid, tig);
    }
    __syncthreads();   // all Wb reads done before next stream overwrites
    {
        float acc[2][4][4];
        gemm_streamW(As, Wb, Wkj_t, tid, warp_m, warp_n, gid, tig, acc);
        epilogue_tf32<M_SILU_MUL>(acc, bkj, g_rbfh, xkj, 128, brow, M,
                                  warp_m, warp_n, gid, tig);
    }
}

// ---------------------------------------------------------------------------
// Stage B1: y[e, j*128+n] = sum_k xkj[e,k]*Wt[j,k,n], stored fp16.
// A-tile reused over the 8 j-slabs.
// ---------------------------------------------------------------------------
__global__ void __launch_bounds__(NTHR, 3)
ygemm_tf32(const float* __restrict__ xkj, uint32_t* __restrict__ Y, int M) {
    extern __shared__ uint32_t smu[];
    uint32_t* As = smu;
    uint32_t* Wb = smu + 64 * AS_LD;
    const int tid = threadIdx.x, brow = blockIdx.x * 64;
    const int warp = tid >> 5, lane = tid & 31;
    const int warp_m = warp >> 2, warp_n = warp & 3;
    const int gid = lane >> 2, tig = lane & 3;

    load_convert_A(xkj, As, brow, M, tid);

#pragma unroll 1
    for (int j = 0; j < 8; j++) {
        float acc[2][4][4];
        gemm_streamW(As, Wb, g_Wt + j * 16384, tid, warp_m, warp_n, gid, tig, acc);
        // fp16 epilogue: pack (n, n+1) pairs into one uint32
#pragma unroll
        for (int mt = 0; mt < 2; mt++) {
            int rbase = brow + warp_m * 32 + mt * 16 + gid;
#pragma unroll
            for (int half = 0; half < 2; half++) {
                int row = rbase + half * 8;
                if (row >= M) continue;
#pragma unroll
                for (int nt = 0; nt < 4; nt++) {
                    int wi = warp_n * 16 + nt * 4 + tig;   // (n>>1)
                    __half2 p = __float22half2_rn(
                        make_float2(acc[mt][nt][half * 2],
                                    acc[mt][nt][half * 2 + 1]));
                    Y[(size_t)row * 512 + j * 64 + wi] = *(uint32_t*)&p;
                }
            }
        }
        __syncthreads();   // Wb reads done before next j's stream
    }
}

// ---------------------------------------------------------------------------
// Combine + scatter: one warp per triplet, fp16 y.
//   lane handles n = lane*4 .. lane*4+3
// ---------------------------------------------------------------------------
__global__ void __launch_bounds__(256)
combine_kernel(const uint32_t* __restrict__ Y,
               const int* __restrict__ idx_kj, const int* __restrict__ idx_ji,
               float* __restrict__ h, int T) {
    int t = blockIdx.x * 8 + (threadIdx.x >> 5);
    if (t >= T) return;
    int lane = threadIdx.x & 31;

    int ekj = __ldg(&idx_kj[t]);
    int eji = __ldg(&idx_ji[t]);
    const float4* s4 = (const float4*)(g_sbfh + (size_t)t * 8);
    float4 sA = s4[0], sB = s4[1];
    float s[8] = {sA.x, sA.y, sA.z, sA.w, sB.x, sB.y, sB.z, sB.w};

    const uint2* yr = (const uint2*)(Y + (size_t)ekj * 512);
    float a0 = 0.f, a1 = 0.f, a2 = 0.f, a3 = 0.f;
#pragma unroll
    for (int j = 0; j < 8; j++) {
        uint2 w = __ldg(&yr[j * 32 + lane]);
        float2 lo = __half22float2(*(__half2*)&w.x);
        float2 hi = __half22float2(*(__half2*)&w.y);
        a0 += s[j] * lo.x;
        a1 += s[j] * lo.y;
        a2 += s[j] * hi.x;
        a3 += s[j] * hi.y;
    }
    atomicAdd(&((float4*)h)[(size_t)eji * 32 + lane],
              make_float4(a0, a1, a2, a3));
}

// ---------------------------------------------------------------------------
// Host launcher
// ---------------------------------------------------------------------------
extern "C" void kernel_launch(void* const* d_in, const int* in_sizes, int n_in,
                              void* d_out, int out_size) {
    const float* x      = (const float*)d_in[0];
    const float* rbf    = (const float*)d_in[1];
    const float* sbf    = (const float*)d_in[2];
    const int*   idx_kj = (const int*)d_in[3];
    const int*   idx_ji = (const int*)d_in[4];
    const float* W_rbf  = (const float*)d_in[5];
    const float* W_sbf  = (const float*)d_in[6];
    const float* Wkj    = (const float*)d_in[7];
    const float* bkj    = (const float*)d_in[8];
    const float* Wji    = (const float*)d_in[9];
    const float* bji    = (const float*)d_in[10];
    const float* Wbil   = (const float*)d_in[11];
    const float* bW1    = (const float*)d_in[12];
    const float* bb1    = (const float*)d_in[13];
    const float* bW2    = (const float*)d_in[14];
    const float* bb2    = (const float*)d_in[15];
    const float* Wlin   = (const float*)d_in[16];
    const float* blin   = (const float*)d_in[17];
    const float* aW1    = (const float*)d_in[18];
    const float* ab1    = (const float*)d_in[19];
    const float* aW2    = (const float*)d_in[20];
    const float* ab2    = (const float*)d_in[21];
    const float* Wout   = (const float*)d_in[22];
    const float* bout   = (const float*)d_in[23];
    float* out = (float*)d_out;

    const int E = in_sizes[0] / 128;
    const int T = in_sizes[3];

    float *xkj, *h, *tmp;
    uint32_t *wtf, *y;
    cudaGetSymbolAddress((void**)&xkj, g_xkj);
    cudaGetSymbolAddress((void**)&h,   g_h);
    cudaGetSymbolAddress((void**)&tmp, g_tmp);
    cudaGetSymbolAddress((void**)&y,   g_y);
    cudaGetSymbolAddress((void**)&wtf, g_wtf);

    cudaFuncSetAttribute(tf32_gemm<M_SILU>,     cudaFuncAttributeMaxDynamicSharedMemorySize, SMEM_TF32);
    cudaFuncSetAttribute(tf32_gemm<M_SILU_ADD>, cudaFuncAttributeMaxDynamicSharedMemorySize, SMEM_TF32);
    cudaFuncSetAttribute(dualA_tf32,            cudaFuncAttributeMaxDynamicSharedMemorySize, SMEM_TF32);
    cudaFuncSetAttribute(ygemm_tf32,            cudaFuncAttributeMaxDynamicSharedMemorySize, SMEM_TF32);

    // Stage 0: preps
    WSrc ws;
    ws.p[0] = Wji;  ws.p[1] = Wkj;
    ws.p[2] = bW1;  ws.p[3] = bW2;
    ws.p[4] = Wlin;
    ws.p[5] = aW1;          ws.p[6] = aW2;
    ws.p[7] = aW1 + 16384;  ws.p[8] = aW2 + 16384;
    ws.p[9] = Wout;
    convert_weights<<<(10 * 16384 + 255) / 256, 256>>>(ws);
    transpose_wbil<<<(8 * 128 * 128 + 255) / 256, 256>>>(Wbil);
    rbfh_kernel<<<(E * 128 + 255) / 256, 256>>>(rbf, W_rbf, E);
    sbfh_kernel<<<(T + 255) / 256, 256>>>(sbf, W_sbf, T);

    const int gE = (E + 63) / 64;
    const uint32_t* WjiT  = wtf + 0 * 16384;
    const uint32_t* WkjT  = wtf + 1 * 16384;
    const uint32_t* bW1T  = wtf + 2 * 16384;
    const uint32_t* bW2T  = wtf + 3 * 16384;
    const uint32_t* WlinT = wtf + 4 * 16384;
    const uint32_t* aW1T0 = wtf + 5 * 16384;
    const uint32_t* aW2T0 = wtf + 6 * 16384;
    const uint32_t* aW1T1 = wtf + 7 * 16384;
    const uint32_t* aW2T1 = wtf + 8 * 16384;
    const uint32_t* WoutT = wtf + 9 * 16384;

    // Stage A
    dualA_tf32<<<gE, NTHR, SMEM_TF32>>>(x, WjiT, bji, WkjT, bkj, h, xkj, E);

    // Stage B1: y precompute (fp16)
    ygemm_tf32<<<gE, NTHR, SMEM_TF32>>>(xkj, y, E);

    // Stage B2: combine + scatter into h  => h = x_ji + agg
    combine_kernel<<<(T + 7) / 8, 256>>>(y, idx_kj, idx_ji, h, T);

    // Stage C: h += silu(silu(h@bW1+bb1)@bW2+bb2)
    tf32_gemm<M_SILU><<<gE, NTHR, SMEM_TF32>>>(h,   bW1T, bb1, nullptr, tmp, 128, E);
    tf32_gemm<M_SILU_ADD><<<gE, NTHR, SMEM_TF32>>>(tmp, bW2T, bb2, h,    h,   128, E);

    // Stage D: h = silu(h@Wlin+blin) + x
    tf32_gemm<M_SILU_ADD><<<gE, NTHR, SMEM_TF32>>>(h, WlinT, blin, x, h, 128, E);

    // Stage E (2x)
    tf32_gemm<M_SILU><<<gE, NTHR, SMEM_TF32>>>(h,   aW1T0, ab1,       nullptr, tmp, 128, E);
    tf32_gemm<M_SILU_ADD><<<gE, NTHR, SMEM_TF32>>>(tmp, aW2T0, ab2,       h,   h,   128, E);
    tf32_gemm<M_SILU><<<gE, NTHR, SMEM_TF32>>>(h,   aW1T1, ab1 + 128, nullptr, tmp, 128, E);
    tf32_gemm<M_SILU_ADD><<<gE, NTHR, SMEM_TF32>>>(tmp, aW2T1, ab2 + 128, h,   h,   128, E);

    // Stage F: out = silu(h@Wout+bout)
    tf32_gemm<M_SILU><<<gE, NTHR, SMEM_TF32>>>(h, WoutT, bout, nullptr, out, 128, E);
}